// round 9
// baseline (speedup 1.0000x reference)
#include <cuda_runtime.h>
#include <cuda_fp16.h>
#include <cstdint>

// ---------------------------------------------------------------------------
// Problem constants
// ---------------------------------------------------------------------------
#define NUM_MODALS 4
#define SHARED_IDX 3
#define CDIM       768
#define RANK       16
#define ROWS_PER_M 8192
#define TOTAL_ROWS 32768

// fp16 operand storage (device globals = allowed scratch)
__device__ __half g_Xq[TOTAL_ROWS * CDIM];
__device__ __half g_Wq[NUM_MODALS * CDIM * CDIM];

// ---------------------------------------------------------------------------
// Helpers
// ---------------------------------------------------------------------------
__device__ __forceinline__ uint32_t smem_u32(const void* p) {
    uint32_t a;
    asm("{ .reg .u64 t; cvta.to.shared.u64 t, %1; cvt.u32.u64 %0, t; }"
        : "=r"(a) : "l"(p));
    return a;
}
__device__ __forceinline__ void cp_async16(uint32_t dst, const void* src) {
    asm volatile("cp.async.cg.shared.global [%0], [%1], 16;"
                 :: "r"(dst), "l"(src) : "memory");
}
__device__ __forceinline__ void cp_commit() {
    asm volatile("cp.async.commit_group;" ::: "memory");
}
template <int N>
__device__ __forceinline__ void cp_wait() {
    asm volatile("cp.async.wait_group %0;" :: "n"(N) : "memory");
}
__device__ __forceinline__ void ldm_x4(uint32_t& r0, uint32_t& r1,
                                       uint32_t& r2, uint32_t& r3,
                                       uint32_t addr) {
    asm volatile("ldmatrix.sync.aligned.m8n8.x4.shared.b16 {%0,%1,%2,%3}, [%4];"
                 : "=r"(r0), "=r"(r1), "=r"(r2), "=r"(r3) : "r"(addr));
}
__device__ __forceinline__ void mma_f16(float& d0, float& d1, float& d2, float& d3,
                                        uint32_t a0, uint32_t a1, uint32_t a2, uint32_t a3,
                                        uint32_t b0, uint32_t b1) {
    asm volatile("mma.sync.aligned.m16n8k16.row.col.f32.f16.f16.f32 "
                 "{%0,%1,%2,%3}, {%4,%5,%6,%7}, {%8,%9}, {%0,%1,%2,%3};"
                 : "+f"(d0), "+f"(d1), "+f"(d2), "+f"(d3)
                 : "r"(a0), "r"(a1), "r"(a2), "r"(a3), "r"(b0), "r"(b1));
}

// ---------------------------------------------------------------------------
// Kernel 1: fused prep.
//   blocks [0, XBLK)      : convert x -> fp16 (float4 vectorized)
//   blocks [XBLK, TOTALB) : W_eff = Wp + Bw3*A3 + Bwm*Am -> fp16
// ---------------------------------------------------------------------------
#define XQUADS (TOTAL_ROWS * CDIM / 4)            // 6291456
#define XBLK   (XQUADS / 256)                     // 24576
#define WELEMS (NUM_MODALS * CDIM * CDIM)         // 2359296
#define WBLK   (WELEMS / 256)                     // 9216
#define TOTALB (XBLK + WBLK)                      // 33792

__global__ __launch_bounds__(256)
void prep_kernel(const float* __restrict__ x,
                 const float* __restrict__ Wp,
                 const float* __restrict__ A,
                 const float* __restrict__ Bw) {
    const int b = blockIdx.x;
    if (b < XBLK) {
        const int i = b * 256 + threadIdx.x;       // quad index
        float4 v = reinterpret_cast<const float4*>(x)[i];
        __half2* H = reinterpret_cast<__half2*>(g_Xq);
        H[i * 2 + 0] = __half2(__float2half(v.x), __float2half(v.y));
        H[i * 2 + 1] = __half2(__float2half(v.z), __float2half(v.w));
    } else {
        const int idx = (b - XBLK) * 256 + threadIdx.x;
        const int c = idx % CDIM;
        const int o = (idx / CDIM) % CDIM;
        const int m = idx / (CDIM * CDIM);

        const float* A3 = A + SHARED_IDX * RANK * CDIM;
        const float* B3 = Bw + SHARED_IDX * CDIM * RANK;
        const float* Am = A + m * RANK * CDIM;
        const float* Bm = Bw + m * CDIM * RANK;

        float s = Wp[o * CDIM + c];
#pragma unroll
        for (int r = 0; r < RANK; r++) {
            s += B3[o * RANK + r] * A3[r * CDIM + c];
            s += Bm[o * RANK + r] * Am[r * CDIM + c];
        }
        g_Wq[idx] = __float2half(s);
    }
}

// ---------------------------------------------------------------------------
// Kernel 2: fp16 GEMM via mma.sync (fp32 accumulate).
//   out[row][o] = sum_c x[row][c]*Weff[m][o][c] + bp[o]
// CTA tile 128x128, 256 threads (8 warps, 2x4), warp tile 64x32.
// K-chunk 32, 4-stage cp.async pipeline, 2 CTAs/SM (16 warps/SM).
// ---------------------------------------------------------------------------
#define BM     128
#define KC2    32                 // fp16 K elems per chunk
#define NCHK   (CDIM / KC2)       // 24
#define LDT    80                 // smem bytes per tile row (64 data + 16 pad)
#define ATB    (BM * LDT)         // 10240 bytes (A tile)
#define BTB    (128 * LDT)        // 10240 bytes (B tile)
#define STB    (ATB + BTB)        // 20480 bytes per stage
#define OFF_A  0
#define OFF_B  ATB
#define STAGES 4
#define SMEM_TOTAL (STAGES * STB) // 81920  -> 2 CTAs/SM

__device__ __forceinline__ void issue_chunk(const __half* __restrict__ xq,
                                            const __half* __restrict__ wq,
                                            int row0, int col0, int kbase,
                                            uint32_t sstage, int tid) {
    // A tile: 128 rows x 64B = 512 x 16B transfers
#pragma unroll
    for (int i = 0; i < 2; i++) {
        int idx = i * 256 + tid;       // 0..511
        int row = idx >> 2;            // 0..127
        int ch  = idx & 3;
        uint32_t soff = row * LDT + ch * 16;
        size_t goff = (size_t)(row0 + row) * CDIM + kbase + ch * 8;
        cp_async16(sstage + OFF_A + soff, xq + goff);
    }
    // B tile: 128 rows x 64B = 512 x 16B transfers
#pragma unroll
    for (int i = 0; i < 2; i++) {
        int idx = i * 256 + tid;
        int row = idx >> 2;
        int ch  = idx & 3;
        uint32_t soff = row * LDT + ch * 16;
        size_t goff = (size_t)(col0 + row) * CDIM + kbase + ch * 8;
        cp_async16(sstage + OFF_B + soff, wq + goff);
    }
    cp_commit();
}

__global__ __launch_bounds__(256, 2)
void lora_mma_gemm(const float* __restrict__ bp, float* __restrict__ out) {
    extern __shared__ char smem[];
    const uint32_t sbase = smem_u32(smem);
    const int tid  = threadIdx.x;
    const int wid  = tid >> 5;
    const int lane = tid & 31;
    const int warp_m = wid >> 2;       // 0..1  (64 rows each)
    const int warp_n = wid & 3;        // 0..3  (32 cols each)

    const int row0 = blockIdx.y * BM;
    const int col0 = blockIdx.x * 128;
    const int modality = row0 / ROWS_PER_M;
    const __half* Wq = g_Wq + (size_t)modality * CDIM * CDIM;

    float acc[4][4][4];
#pragma unroll
    for (int i = 0; i < 4; i++)
#pragma unroll
        for (int j = 0; j < 4; j++)
#pragma unroll
            for (int r = 0; r < 4; r++) acc[i][j][r] = 0.f;

    // ldmatrix lane addressing
    const int mat = lane >> 3;         // which 8x8 tile (0..3)
    const int mr  = lane & 7;          // row within tile
    const int a_row  = warp_m * 64 + (mat & 1) * 8 + mr;     // + i*16
    const int a_colb = (mat >> 1) * 16;                      // bytes, + kk*32
    const int b_row  = warp_n * 32 + (mat >> 1) * 8 + mr;    // + jh*16
    const int b_colb = (mat & 1) * 16;                       // bytes, + kk*32

    // Prologue: 3 chunks in flight
    issue_chunk(g_Xq, Wq, row0, col0, 0,       sbase + 0 * STB, tid);
    issue_chunk(g_Xq, Wq, row0, col0, KC2,     sbase + 1 * STB, tid);
    issue_chunk(g_Xq, Wq, row0, col0, 2 * KC2, sbase + 2 * STB, tid);

    for (int c = 0; c < NCHK; c++) {
        if (c + 1 >= NCHK)      cp_wait<0>();
        else if (c + 2 >= NCHK) cp_wait<1>();
        else                    cp_wait<2>();
        __syncthreads();   // also protects slot (c-1)%4 from the issue below

        if (c + 3 < NCHK)
            issue_chunk(g_Xq, Wq, row0, col0, (c + 3) * KC2,
                        sbase + ((c + 3) % STAGES) * STB, tid);

        const uint32_t st = sbase + (c % STAGES) * STB;
        const uint32_t sA = st + OFF_A, sB = st + OFF_B;

#pragma unroll
        for (int kk = 0; kk < 2; kk++) {
            uint32_t bq[4][2];
#pragma unroll
            for (int jh = 0; jh < 2; jh++) {   // 2 x (two 16-col frag pairs)
                uint32_t boff = (uint32_t)(b_row + jh * 16) * LDT + kk * 32 + b_colb;
                uint32_t r0, r1, r2, r3;
                ldm_x4(r0, r1, r2, r3, sB + boff);
                bq[2 * jh][0] = r0; bq[2 * jh][1] = r1;
                bq[2 * jh + 1][0] = r2; bq[2 * jh + 1][1] = r3;
            }
#pragma unroll
            for (int i = 0; i < 4; i++) {
                uint32_t aoff = (uint32_t)(a_row + i * 16) * LDT + kk * 32 + a_colb;
                uint32_t a0, a1, a2, a3;
                ldm_x4(a0, a1, a2, a3, sA + aoff);
#pragma unroll
                for (int j = 0; j < 4; j++)
                    mma_f16(acc[i][j][0], acc[i][j][1], acc[i][j][2], acc[i][j][3],
                            a0, a1, a2, a3, bq[j][0], bq[j][1]);
            }
        }
    }
    __syncthreads();

    // Epilogue: bias + store. mma C frag: lane t -> rows (t/4, t/4+8), cols (t%4)*2..+1
    const int gID = lane >> 2;
    const int tg  = lane & 3;
#pragma unroll
    for (int j = 0; j < 4; j++) {
        const int col = col0 + warp_n * 32 + j * 8 + tg * 2;
        const float2 bb = *reinterpret_cast<const float2*>(bp + col);
#pragma unroll
        for (int i = 0; i < 4; i++) {
            const int row = row0 + warp_m * 64 + i * 16 + gID;
            float2 v0 = make_float2(acc[i][j][0] + bb.x, acc[i][j][1] + bb.y);
            float2 v1 = make_float2(acc[i][j][2] + bb.x, acc[i][j][3] + bb.y);
            *reinterpret_cast<float2*>(out + (size_t)row * CDIM + col) = v0;
            *reinterpret_cast<float2*>(out + (size_t)(row + 8) * CDIM + col) = v1;
        }
    }
}

// ---------------------------------------------------------------------------
// Launch
// ---------------------------------------------------------------------------
extern "C" void kernel_launch(void* const* d_in, const int* in_sizes, int n_in,
                              void* d_out, int out_size) {
    const float* x  = (const float*)d_in[0];  // [32, 1024, 768]
    const float* Wp = (const float*)d_in[1];  // [768, 768]
    const float* bp = (const float*)d_in[2];  // [768]
    const float* A  = (const float*)d_in[3];  // [4, 16, 768]
    const float* Bw = (const float*)d_in[4];  // [4, 768, 16]
    float* out = (float*)d_out;

    prep_kernel<<<TOTALB, 256>>>(x, Wp, A, Bw);
    {
        cudaFuncSetAttribute(lora_mma_gemm,
                             cudaFuncAttributeMaxDynamicSharedMemorySize, SMEM_TOTAL);
        dim3 grid(CDIM / 128, TOTAL_ROWS / BM);  // (6, 256)
        lora_mma_gemm<<<grid, 256, SMEM_TOTAL>>>(bp, out);
    }
}

// round 10
// speedup vs baseline: 1.6129x; 1.6129x over previous
#include <cuda_runtime.h>
#include <cuda_fp16.h>
#include <cstdint>

// ---------------------------------------------------------------------------
// Problem constants
// ---------------------------------------------------------------------------
#define NUM_MODALS 4
#define SHARED_IDX 3
#define CDIM       768
#define RANK       16
#define ROWS_PER_M 8192
#define TOTAL_ROWS 32768

// fp16 operand storage (device globals = allowed scratch)
__device__ __half g_Xq[TOTAL_ROWS * CDIM];
__device__ __half g_Wq[NUM_MODALS * CDIM * CDIM];

// ---------------------------------------------------------------------------
// Helpers
// ---------------------------------------------------------------------------
__device__ __forceinline__ uint32_t smem_u32(const void* p) {
    uint32_t a;
    asm("{ .reg .u64 t; cvta.to.shared.u64 t, %1; cvt.u32.u64 %0, t; }"
        : "=r"(a) : "l"(p));
    return a;
}
__device__ __forceinline__ void cp_async16(uint32_t dst, const void* src) {
    asm volatile("cp.async.cg.shared.global [%0], [%1], 16;"
                 :: "r"(dst), "l"(src) : "memory");
}
__device__ __forceinline__ void cp_commit() {
    asm volatile("cp.async.commit_group;" ::: "memory");
}
template <int N>
__device__ __forceinline__ void cp_wait() {
    asm volatile("cp.async.wait_group %0;" :: "n"(N) : "memory");
}
__device__ __forceinline__ void ldm_x4(uint32_t& r0, uint32_t& r1,
                                       uint32_t& r2, uint32_t& r3,
                                       uint32_t addr) {
    asm volatile("ldmatrix.sync.aligned.m8n8.x4.shared.b16 {%0,%1,%2,%3}, [%4];"
                 : "=r"(r0), "=r"(r1), "=r"(r2), "=r"(r3) : "r"(addr));
}
__device__ __forceinline__ void mma_f16(float& d0, float& d1, float& d2, float& d3,
                                        uint32_t a0, uint32_t a1, uint32_t a2, uint32_t a3,
                                        uint32_t b0, uint32_t b1) {
    asm volatile("mma.sync.aligned.m16n8k16.row.col.f32.f16.f16.f32 "
                 "{%0,%1,%2,%3}, {%4,%5,%6,%7}, {%8,%9}, {%0,%1,%2,%3};"
                 : "+f"(d0), "+f"(d1), "+f"(d2), "+f"(d3)
                 : "r"(a0), "r"(a1), "r"(a2), "r"(a3), "r"(b0), "r"(b1));
}

// ---------------------------------------------------------------------------
// Kernel 1: fused prep.
//   blocks [0, XBLK)      : convert x -> fp16 (float4 vectorized)
//   blocks [XBLK, TOTALB) : W_eff = Wp + Bw3*A3 + Bwm*Am -> fp16
// ---------------------------------------------------------------------------
#define XQUADS (TOTAL_ROWS * CDIM / 4)            // 6291456
#define XBLK   (XQUADS / 256)                     // 24576
#define WELEMS (NUM_MODALS * CDIM * CDIM)         // 2359296
#define WBLK   (WELEMS / 256)                     // 9216
#define TOTALB (XBLK + WBLK)                      // 33792

__global__ __launch_bounds__(256)
void prep_kernel(const float* __restrict__ x,
                 const float* __restrict__ Wp,
                 const float* __restrict__ A,
                 const float* __restrict__ Bw) {
    const int b = blockIdx.x;
    if (b < XBLK) {
        const int i = b * 256 + threadIdx.x;       // quad index
        float4 v = reinterpret_cast<const float4*>(x)[i];
        __half2* H = reinterpret_cast<__half2*>(g_Xq);
        H[i * 2 + 0] = __half2(__float2half(v.x), __float2half(v.y));
        H[i * 2 + 1] = __half2(__float2half(v.z), __float2half(v.w));
    } else {
        const int idx = (b - XBLK) * 256 + threadIdx.x;
        const int c = idx % CDIM;
        const int o = (idx / CDIM) % CDIM;
        const int m = idx / (CDIM * CDIM);

        const float* A3 = A + SHARED_IDX * RANK * CDIM;
        const float* B3 = Bw + SHARED_IDX * CDIM * RANK;
        const float* Am = A + m * RANK * CDIM;
        const float* Bm = Bw + m * CDIM * RANK;

        float s = Wp[o * CDIM + c];
#pragma unroll
        for (int r = 0; r < RANK; r++) {
            s += B3[o * RANK + r] * A3[r * CDIM + c];
            s += Bm[o * RANK + r] * Am[r * CDIM + c];
        }
        g_Wq[idx] = __float2half(s);
    }
}

// ---------------------------------------------------------------------------
// Kernel 2: fp16 GEMM via mma.sync (fp32 accumulate).
//   out[row][o] = sum_c x[row][c]*Weff[m][o][c] + bp[o]
// CTA tile 128x128, 128 threads (4 warps, 2x2), warp tile 64x64.
// K-chunk 64 (128B rows), 3-stage cp.async pipeline, 2 CTAs/SM.
// ---------------------------------------------------------------------------
#define BM     128
#define KC2    64                 // fp16 K elems per chunk
#define NCHK   (CDIM / KC2)       // 12
#define LDT    144                // smem bytes per tile row (128 data + 16 pad)
#define ATB    (BM * LDT)         // 18432 bytes (A tile)
#define BTB    (128 * LDT)        // 18432 bytes (B tile)
#define STB    (ATB + BTB)        // 36864 bytes per stage
#define OFF_A  0
#define OFF_B  ATB
#define STAGES 3
#define SMEM_TOTAL (STAGES * STB) // 110592 -> 2 CTAs/SM (221184 <= 228KB)

__device__ __forceinline__ void issue_chunk(const __half* __restrict__ xq,
                                            const __half* __restrict__ wq,
                                            int row0, int col0, int kbase,
                                            uint32_t sstage, int tid) {
    // A tile: 128 rows x 128B = 1024 x 16B transfers
#pragma unroll
    for (int i = 0; i < 8; i++) {
        int idx = i * 128 + tid;       // 0..1023
        int row = idx >> 3;            // 0..127
        int ch  = idx & 7;             // 16B chunk within 128B row
        uint32_t soff = row * LDT + ch * 16;
        size_t goff = (size_t)(row0 + row) * CDIM + kbase + ch * 8;
        cp_async16(sstage + OFF_A + soff, xq + goff);
    }
    // B tile: 128 rows x 128B = 1024 x 16B transfers
#pragma unroll
    for (int i = 0; i < 8; i++) {
        int idx = i * 128 + tid;
        int row = idx >> 3;
        int ch  = idx & 7;
        uint32_t soff = row * LDT + ch * 16;
        size_t goff = (size_t)(col0 + row) * CDIM + kbase + ch * 8;
        cp_async16(sstage + OFF_B + soff, wq + goff);
    }
    cp_commit();
}

__global__ __launch_bounds__(128, 2)
void lora_mma_gemm(const float* __restrict__ bp, float* __restrict__ out) {
    extern __shared__ char smem[];
    const uint32_t sbase = smem_u32(smem);
    const int tid  = threadIdx.x;
    const int wid  = tid >> 5;
    const int lane = tid & 31;
    const int warp_m = wid >> 1;       // 0..1  (64 rows each)
    const int warp_n = wid & 1;        // 0..1  (64 cols each)

    const int row0 = blockIdx.y * BM;
    const int col0 = blockIdx.x * 128;
    const int modality = row0 / ROWS_PER_M;
    const __half* Wq = g_Wq + (size_t)modality * CDIM * CDIM;

    float acc[4][8][4];
#pragma unroll
    for (int i = 0; i < 4; i++)
#pragma unroll
        for (int j = 0; j < 8; j++)
#pragma unroll
            for (int r = 0; r < 4; r++) acc[i][j][r] = 0.f;

    // ldmatrix lane addressing
    const int mat = lane >> 3;         // which 8x8 tile (0..3)
    const int mr  = lane & 7;          // row within tile
    const int a_row  = warp_m * 64 + (mat & 1) * 8 + mr;     // + i*16
    const int a_colb = (mat >> 1) * 16;                      // bytes, + kk*32
    const int b_row  = warp_n * 64 + (mat >> 1) * 8 + mr;    // + jh*16
    const int b_colb = (mat & 1) * 16;                       // bytes, + kk*32

    // Prologue: 2 chunks in flight
    issue_chunk(g_Xq, Wq, row0, col0, 0,   sbase + 0 * STB, tid);
    issue_chunk(g_Xq, Wq, row0, col0, KC2, sbase + 1 * STB, tid);

    for (int c = 0; c < NCHK; c++) {
        if (c + 1 >= NCHK) cp_wait<0>(); else cp_wait<1>();
        __syncthreads();   // also protects slot (c-1)%3 from the issue below

        if (c + 2 < NCHK)
            issue_chunk(g_Xq, Wq, row0, col0, (c + 2) * KC2,
                        sbase + ((c + 2) % STAGES) * STB, tid);

        const uint32_t st = sbase + (c % STAGES) * STB;
        const uint32_t sA = st + OFF_A, sB = st + OFF_B;

#pragma unroll
        for (int kk = 0; kk < 4; kk++) {          // four k16 slabs per 128B chunk
            uint32_t bq[8][2];
#pragma unroll
            for (int jh = 0; jh < 4; jh++) {      // 4 x 16-col fragments
                uint32_t boff = (uint32_t)(b_row + jh * 16) * LDT + kk * 32 + b_colb;
                uint32_t r0, r1, r2, r3;
                ldm_x4(r0, r1, r2, r3, sB + boff);
                bq[2 * jh][0] = r0; bq[2 * jh][1] = r1;
                bq[2 * jh + 1][0] = r2; bq[2 * jh + 1][1] = r3;
            }
#pragma unroll
            for (int i = 0; i < 4; i++) {
                uint32_t aoff = (uint32_t)(a_row + i * 16) * LDT + kk * 32 + a_colb;
                uint32_t a0, a1, a2, a3;
                ldm_x4(a0, a1, a2, a3, sA + aoff);
#pragma unroll
                for (int j = 0; j < 8; j++)
                    mma_f16(acc[i][j][0], acc[i][j][1], acc[i][j][2], acc[i][j][3],
                            a0, a1, a2, a3, bq[j][0], bq[j][1]);
            }
        }
    }
    __syncthreads();

    // Epilogue: bias + store. mma C frag: lane t -> rows (t/4, t/4+8), cols (t%4)*2..+1
    const int gID = lane >> 2;
    const int tg  = lane & 3;
#pragma unroll
    for (int j = 0; j < 8; j++) {
        const int col = col0 + warp_n * 64 + j * 8 + tg * 2;
        const float2 bb = *reinterpret_cast<const float2*>(bp + col);
#pragma unroll
        for (int i = 0; i < 4; i++) {
            const int row = row0 + warp_m * 64 + i * 16 + gID;
            float2 v0 = make_float2(acc[i][j][0] + bb.x, acc[i][j][1] + bb.y);
            float2 v1 = make_float2(acc[i][j][2] + bb.x, acc[i][j][3] + bb.y);
            *reinterpret_cast<float2*>(out + (size_t)row * CDIM + col) = v0;
            *reinterpret_cast<float2*>(out + (size_t)(row + 8) * CDIM + col) = v1;
        }
    }
}

// ---------------------------------------------------------------------------
// Launch
// ---------------------------------------------------------------------------
extern "C" void kernel_launch(void* const* d_in, const int* in_sizes, int n_in,
                              void* d_out, int out_size) {
    const float* x  = (const float*)d_in[0];  // [32, 1024, 768]
    const float* Wp = (const float*)d_in[1];  // [768, 768]
    const float* bp = (const float*)d_in[2];  // [768]
    const float* A  = (const float*)d_in[3];  // [4, 16, 768]
    const float* Bw = (const float*)d_in[4];  // [4, 768, 16]
    float* out = (float*)d_out;

    prep_kernel<<<TOTALB, 256>>>(x, Wp, A, Bw);
    {
        cudaFuncSetAttribute(lora_mma_gemm,
                             cudaFuncAttributeMaxDynamicSharedMemorySize, SMEM_TOTAL);
        dim3 grid(CDIM / 128, TOTAL_ROWS / BM);  // (6, 256)
        lora_mma_gemm<<<grid, 128, SMEM_TOTAL>>>(bp, out);
    }
}